// round 17
// baseline (speedup 1.0000x reference)
#include <cuda_runtime.h>
#include <cuda_bf16.h>
#include <cstdint>

// Problem constants
#define PB  16
#define PTV 128
#define PTH 64
#define PF  512
#define PH  512
#define PD  256
#define KDIM 512

#define MTILES 48
#define KITERS 32

// ---------------------------------------------------------------------------
// Device scratch
// ---------------------------------------------------------------------------
__device__ uint4 g_Afrag[MTILES * KITERS * 4 * 2 * 32];
__device__ uint4 g_Bfrag[2 * KITERS * 32 * 32];

__device__ float g_WvT[PB * PD * PTV];   // [b][d][t]
__device__ float g_Uhb[PB * PTH * PD];   // [b][s][d]
__device__ float g_beta[PB * PTH * PTV]; // [b][s][t]

__device__ __forceinline__ float tanh_approx(float x) {
    float r; asm("tanh.approx.f32 %0, %1;" : "=f"(r) : "f"(x)); return r;
}
__device__ __forceinline__ uint32_t smem_u32(const void* p) {
    uint32_t a;
    asm("{ .reg .u64 t; cvta.to.shared.u64 t, %1; cvt.u32.u64 %0, t; }" : "=r"(a) : "l"(p));
    return a;
}
__device__ __forceinline__ void cp_async16(uint32_t smem_addr, const void* gptr) {
    asm volatile("cp.async.cg.shared.global [%0], [%1], 16;" :: "r"(smem_addr), "l"(gptr));
}
#define CP_COMMIT() asm volatile("cp.async.commit_group;" ::: "memory")
#define CP_WAIT(N)  asm volatile("cp.async.wait_group %0;" :: "n"(N) : "memory")

// Split-pair: packed bf16-hi of (a,b) [lo half = a]; lop gets residual pair.
__device__ __forceinline__ uint32_t splitpair(float a, float b, uint32_t& lop) {
    uint32_t hp;
    asm("cvt.rn.bf16x2.f32 %0, %1, %2;" : "=r"(hp) : "f"(b), "f"(a));
    float ha = __uint_as_float(hp << 16);
    float hb = __uint_as_float(hp & 0xFFFF0000u);
    float la = a - ha;
    float lb = b - hb;
    asm("cvt.rn.bf16x2.f32 %0, %1, %2;" : "=r"(lop) : "f"(lb), "f"(la));
    return hp;
}

__device__ __forceinline__ void mma_bf16(float* c, uint32_t a0, uint32_t a1, uint32_t a2, uint32_t a3,
                                         uint32_t b0, uint32_t b1) {
    asm volatile(
        "mma.sync.aligned.m16n8k16.row.col.f32.bf16.bf16.f32 "
        "{%0,%1,%2,%3}, {%4,%5,%6,%7}, {%8,%9}, {%0,%1,%2,%3};"
        : "+f"(c[0]), "+f"(c[1]), "+f"(c[2]), "+f"(c[3])
        : "r"(a0), "r"(a1), "r"(a2), "r"(a3), "r"(b0), "r"(b1));
}

// ---------------------------------------------------------------------------
// Prep kernel (round-11 version: 1024 CTAs, no smem)
// ---------------------------------------------------------------------------
__global__ __launch_bounds__(256) void prep_kernel(
    const float* __restrict__ v, const float* __restrict__ h,
    const float* __restrict__ W, const float* __restrict__ U)
{
    int gid = blockIdx.x * 256 + threadIdx.x;
    if (gid < 196608) {
        int lane = gid & 31;
        int mf   = (gid >> 5) & 3;
        int kit  = (gid >> 7) & 31;
        int tile = gid >> 12;

        int rloc = tile * 64 + mf * 16 + (lane >> 2);
        const float* r0p;
        if (tile < 32) r0p = v + (size_t)rloc * KDIM;
        else           r0p = h + (size_t)(rloc - 2048) * KDIM;
        const float* r1p = r0p + 8 * KDIM;
        int k0 = kit * 16 + (lane & 3) * 2;

        float2 x00 = *reinterpret_cast<const float2*>(r0p + k0);
        float2 x10 = *reinterpret_cast<const float2*>(r1p + k0);
        float2 x08 = *reinterpret_cast<const float2*>(r0p + k0 + 8);
        float2 x18 = *reinterpret_cast<const float2*>(r1p + k0 + 8);

        uint4 vh, vl;
        vh.x = splitpair(x00.x, x00.y, vl.x);
        vh.y = splitpair(x10.x, x10.y, vl.y);
        vh.z = splitpair(x08.x, x08.y, vl.z);
        vh.w = splitpair(x18.x, x18.y, vl.w);

        size_t base = ((((size_t)tile * KITERS + kit) * 4 + mf) * 2) * 32 + lane;
        g_Afrag[base]      = vh;
        g_Afrag[base + 32] = vl;
    } else if (gid < 262144) {
        int item = gid - 196608;
        int lane = item & 31;
        int nf   = (item >> 5) & 31;
        int kit  = (item >> 10) & 31;
        int mat  = item >> 15;

        const float* Bsrc = mat ? U : W;
        int n = nf * 8 + (lane >> 2);
        int k0 = kit * 16 + (lane & 3) * 2;

        float xa = Bsrc[(size_t)(k0 + 0) * PD + n];
        float xb = Bsrc[(size_t)(k0 + 1) * PD + n];
        float xc = Bsrc[(size_t)(k0 + 8) * PD + n];
        float xd = Bsrc[(size_t)(k0 + 9) * PD + n];

        uint4 out;
        out.x = splitpair(xa, xb, out.z);
        out.y = splitpair(xc, xd, out.w);
        g_Bfrag[(((size_t)mat * KITERS + kit) * 32 + nf) * 32 + lane] = out;
    }
}

// ---------------------------------------------------------------------------
// bf16 split-float MMA GEMM (round-11 version)
// ---------------------------------------------------------------------------
__global__ __launch_bounds__(256) void mma_gemm_kernel(const float* __restrict__ bias)
{
    __shared__ __align__(16) char s_raw[32768];
    uint4* sbuf = reinterpret_cast<uint4*>(s_raw);
    const uint32_t sbase = smem_u32(s_raw);

    const int tile  = blockIdx.x >> 2;
    const int ntile = blockIdx.x & 3;
    const int tid   = threadIdx.x;
    const int lane  = tid & 31;
    const int wid   = tid >> 5;
    const int wm    = wid >> 2;
    const int wn    = wid & 3;
    const bool is_v = tile < 32;

    float acc[2][2][4];
#pragma unroll
    for (int mf = 0; mf < 2; mf++)
#pragma unroll
        for (int nf = 0; nf < 2; nf++)
#pragma unroll
            for (int r = 0; r < 4; r++) acc[mf][nf][r] = 0.0f;

    const uint4* Asrc = g_Afrag + (size_t)tile * (KITERS * 256);
    const uint4* Bsrc = g_Bfrag + ((size_t)(is_v ? 0 : 1) * KITERS * 32 + ntile * 8) * 32;

#pragma unroll
    for (int s = 0; s < 3; s++) {
        cp_async16(sbase + (s * 512 + tid) * 16,       Asrc + (size_t)s * 256 + tid);
        cp_async16(sbase + (s * 512 + 256 + tid) * 16, Bsrc + (size_t)s * 1024 + tid);
        CP_COMMIT();
    }

    const int aoff0 = ((wm * 2 + 0) * 2) * 32 + lane;
    const int boff0 = 256 + (wn * 2) * 32 + lane;

#pragma unroll 4
    for (int kit = 0; kit < KITERS; kit++) {
        const int p = kit & 3;
        CP_WAIT(2);
        __syncthreads();
        if (kit + 3 < KITERS) {
            const int s = (kit + 3) & 3;
            cp_async16(sbase + (s * 512 + tid) * 16,       Asrc + (size_t)(kit + 3) * 256 + tid);
            cp_async16(sbase + (s * 512 + 256 + tid) * 16, Bsrc + (size_t)(kit + 3) * 1024 + tid);
        }
        CP_COMMIT();

        const uint4* buf = sbuf + p * 512;
        uint4 Ah[2], Al[2], Bf[2];
        Ah[0] = buf[aoff0];
        Al[0] = buf[aoff0 + 32];
        Ah[1] = buf[aoff0 + 64];
        Al[1] = buf[aoff0 + 96];
        Bf[0] = buf[boff0];
        Bf[1] = buf[boff0 + 32];
#pragma unroll
        for (int mf = 0; mf < 2; mf++) {
#pragma unroll
            for (int nf = 0; nf < 2; nf++) {
                mma_bf16(acc[mf][nf], Ah[mf].x, Ah[mf].y, Ah[mf].z, Ah[mf].w, Bf[nf].x, Bf[nf].y);
                mma_bf16(acc[mf][nf], Ah[mf].x, Ah[mf].y, Ah[mf].z, Ah[mf].w, Bf[nf].z, Bf[nf].w);
                mma_bf16(acc[mf][nf], Al[mf].x, Al[mf].y, Al[mf].z, Al[mf].w, Bf[nf].x, Bf[nf].y);
            }
        }
    }
    __syncthreads();

    const int g  = lane >> 2;
    const int tc = (lane & 3) * 2;

    if (is_v) {
        float (*st)[72] = reinterpret_cast<float (*)[72]>(s_raw);
#pragma unroll
        for (int mf = 0; mf < 2; mf++) {
#pragma unroll
            for (int nf = 0; nf < 2; nf++) {
                int ml = wm * 32 + mf * 16 + g;
                int nl = wn * 16 + nf * 8 + tc;
                st[nl][ml]         = acc[mf][nf][0];
                st[nl + 1][ml]     = acc[mf][nf][1];
                st[nl][ml + 8]     = acc[mf][nf][2];
                st[nl + 1][ml + 8] = acc[mf][nf][3];
            }
        }
        __syncthreads();
        const int b  = tile >> 1;
        const int t0 = (tile & 1) * 64;
        const int d0 = ntile * 64;
        for (int i = tid; i < 64 * 16; i += 256) {
            int d  = i >> 4;
            int m4 = (i & 15) << 2;
            float4 val = *reinterpret_cast<const float4*>(&st[d][m4]);
            *reinterpret_cast<float4*>(
                g_WvT + ((size_t)(b * PD + d0 + d) << 7) + t0 + m4) = val;
        }
    } else {
#pragma unroll
        for (int mf = 0; mf < 2; mf++) {
            int row = (tile - 32) * 64 + wm * 32 + mf * 16 + g;
#pragma unroll
            for (int nf = 0; nf < 2; nf++) {
                int col = ntile * 64 + wn * 16 + nf * 8 + tc;
                float b0 = __ldg(bias + col);
                float b1 = __ldg(bias + col + 1);
                float2 o0 = make_float2(acc[mf][nf][0] + b0, acc[mf][nf][1] + b1);
                float2 o1 = make_float2(acc[mf][nf][2] + b0, acc[mf][nf][3] + b1);
                *reinterpret_cast<float2*>(g_Uhb + (size_t)row * PD + col)       = o0;
                *reinterpret_cast<float2*>(g_Uhb + (size_t)(row + 8) * PD + col) = o1;
            }
        }
    }
}

// ---------------------------------------------------------------------------
// Scores + softmax -> g_beta. Grid (16,16) = 256 CTAs, 256 threads.
// (unchanged from round 16)
// ---------------------------------------------------------------------------
__global__ __launch_bounds__(256) void scores_kernel(
    const float* __restrict__ wvec, float* __restrict__ beta)
{
    const int b = blockIdx.y;
    const int s0 = blockIdx.x * 4;
    const int tid = threadIdx.x;
    const int t = tid & 127;
    const int dh = tid >> 7;

    __shared__ float su[4][PD];
    __shared__ float sw[PD];
    __shared__ float rmax[4][4];
    __shared__ float rsum[4][4];
    __shared__ float spA[4][PTV];
    __shared__ __align__(16) char sraw[32768];

    const uint32_t sb_addr = smem_u32(sraw);

    if (tid < PD) sw[tid] = wvec[tid];
    for (int i = tid; i < 4 * PD; i += 256)
        su[i >> 8][i & 255] = g_Uhb[((size_t)(b * PTH + s0 + (i >> 8)) << 8) + (i & 255)];

    const float4* wsrc = reinterpret_cast<const float4*>(g_WvT + ((size_t)b << 15));
#pragma unroll
    for (int j = 0; j < 4; j++)
        cp_async16(sb_addr + (j * 256 + tid) * 16, wsrc + j * 256 + tid);
    CP_COMMIT();

    float a0 = 0.f, a1 = 0.f, a2 = 0.f, a3 = 0.f;
    for (int c = 0; c < 8; c++) {
        const int p = c & 1;
        CP_WAIT(0);
        __syncthreads();
        if (c + 1 < 8) {
            const float4* src = wsrc + (size_t)(c + 1) * 1024;
            uint32_t dst = sb_addr + (p ^ 1) * 16384;
#pragma unroll
            for (int j = 0; j < 4; j++)
                cp_async16(dst + (j * 256 + tid) * 16, src + j * 256 + tid);
        }
        CP_COMMIT();

        const float* wb = reinterpret_cast<const float*>(sraw + p * 16384); // [32][128]
        const int rbase = dh * 16;
        const int dbase = c * 32 + rbase;
#pragma unroll
        for (int j = 0; j < 16; j += 4) {
            float wv0 = wb[(rbase + j + 0) * 128 + t];
            float wv1 = wb[(rbase + j + 1) * 128 + t];
            float wv2 = wb[(rbase + j + 2) * 128 + t];
            float wv3 = wb[(rbase + j + 3) * 128 + t];
            float4 w4  = *reinterpret_cast<const float4*>(&sw[dbase + j]);
            float4 s0v = *reinterpret_cast<const float4*>(&su[0][dbase + j]);
            float4 s1v = *reinterpret_cast<const float4*>(&su[1][dbase + j]);
            float4 s2v = *reinterpret_cast<const float4*>(&su[2][dbase + j]);
            float4 s3v = *reinterpret_cast<const float4*>(&su[3][dbase + j]);

            a0 = fmaf(w4.x, tanh_approx(s0v.x + wv0), a0);
            a1 = fmaf(w4.x, tanh_approx(s1v.x + wv0), a1);
            a2 = fmaf(w4.x, tanh_approx(s2v.x + wv0), a2);
            a3 = fmaf(w4.x, tanh_approx(s3v.x + wv0), a3);

            a0 = fmaf(w4.y, tanh_approx(s0v.y + wv1), a0);
            a1 = fmaf(w4.y, tanh_approx(s1v.y + wv1), a1);
            a2 = fmaf(w4.y, tanh_approx(s2v.y + wv1), a2);
            a3 = fmaf(w4.y, tanh_approx(s3v.y + wv1), a3);

            a0 = fmaf(w4.z, tanh_approx(s0v.z + wv2), a0);
            a1 = fmaf(w4.z, tanh_approx(s1v.z + wv2), a1);
            a2 = fmaf(w4.z, tanh_approx(s2v.z + wv2), a2);
            a3 = fmaf(w4.z, tanh_approx(s3v.z + wv2), a3);

            a0 = fmaf(w4.w, tanh_approx(s0v.w + wv3), a0);
            a1 = fmaf(w4.w, tanh_approx(s1v.w + wv3), a1);
            a2 = fmaf(w4.w, tanh_approx(s2v.w + wv3), a2);
            a3 = fmaf(w4.w, tanh_approx(s3v.w + wv3), a3);
        }
    }
    __syncthreads();

    if (dh == 1) {
        spA[0][t] = a0; spA[1][t] = a1; spA[2][t] = a2; spA[3][t] = a3;
    }
    __syncthreads();

    float e0, e1, e2, e3;
    const int lane = t & 31;
    const int wq = t >> 5;
    if (dh == 0) {
        a0 += spA[0][t]; a1 += spA[1][t]; a2 += spA[2][t]; a3 += spA[3][t];
        float m0 = a0, m1 = a1, m2 = a2, m3 = a3;
#pragma unroll
        for (int off = 16; off; off >>= 1) {
            m0 = fmaxf(m0, __shfl_xor_sync(0xffffffffu, m0, off));
            m1 = fmaxf(m1, __shfl_xor_sync(0xffffffffu, m1, off));
            m2 = fmaxf(m2, __shfl_xor_sync(0xffffffffu, m2, off));
            m3 = fmaxf(m3, __shfl_xor_sync(0xffffffffu, m3, off));
        }
        if (lane == 0) { rmax[0][wq] = m0; rmax[1][wq] = m1; rmax[2][wq] = m2; rmax[3][wq] = m3; }
    }
    __syncthreads();
    if (dh == 0) {
        float m0 = fmaxf(fmaxf(rmax[0][0], rmax[0][1]), fmaxf(rmax[0][2], rmax[0][3]));
        float m1 = fmaxf(fmaxf(rmax[1][0], rmax[1][1]), fmaxf(rmax[1][2], rmax[1][3]));
        float m2 = fmaxf(fmaxf(rmax[2][0], rmax[2][1]), fmaxf(rmax[2][2], rmax[2][3]));
        float m3 = fmaxf(fmaxf(rmax[3][0], rmax[3][1]), fmaxf(rmax[3][2], rmax[3][3]));
        e0 = __expf(a0 - m0); e1 = __expf(a1 - m1);
        e2 = __expf(a2 - m2); e3 = __expf(a3 - m3);
        float s0v = e0, s1v = e1, s2v = e2, s3v = e3;
#pragma unroll
        for (int off = 16; off; off >>= 1) {
            s0v += __shfl_xor_sync(0xffffffffu, s0v, off);
            s1v += __shfl_xor_sync(0xffffffffu, s1v, off);
            s2v += __shfl_xor_sync(0xffffffffu, s2v, off);
            s3v += __shfl_xor_sync(0xffffffffu, s3v, off);
        }
        if (lane == 0) { rsum[0][wq] = s0v; rsum[1][wq] = s1v; rsum[2][wq] = s2v; rsum[3][wq] = s3v; }
    }
    __syncthreads();
    if (dh == 0) {
        float i0 = 1.0f / ((rsum[0][0] + rsum[0][1]) + (rsum[0][2] + rsum[0][3]));
        float i1 = 1.0f / ((rsum[1][0] + rsum[1][1]) + (rsum[1][2] + rsum[1][3]));
        float i2 = 1.0f / ((rsum[2][0] + rsum[2][1]) + (rsum[2][2] + rsum[2][3]));
        float i3 = 1.0f / ((rsum[3][0] + rsum[3][1]) + (rsum[3][2] + rsum[3][3]));
        float* bout = beta + ((size_t)(b * PTH + s0) << 7) + t;
        bout[0]       = e0 * i0;
        bout[128]     = e1 * i1;
        bout[256]     = e2 * i2;
        bout[384]     = e3 * i3;
    }
}

// ---------------------------------------------------------------------------
// Context: u[b][s][f] = sum_t beta[b][s][t] * v[b][t][f]
// Grid (4 f-chunks, 8 s-groups of 8, 16 b) = 512 CTAs, 256 threads.
// Thread = (f4 = tid&31, ts = tid>>5). Each thread carries ALL 8 s of its
// group (8 float4 accs) over its own t-rows (2 per 16-row chunk) -> every
// staged v word is LDS-read exactly ONCE; beta via broadcast LDS.
// Partials combined across ts via 32KB smem matrix (overlaid on staging).
// ---------------------------------------------------------------------------
__global__ __launch_bounds__(256) void context_kernel(
    const float* __restrict__ v, const float* __restrict__ beta,
    float* __restrict__ u)
{
    const int b  = blockIdx.z;
    const int s0 = blockIdx.y * 8;
    const int f0 = blockIdx.x * 128;
    const int tid = threadIdx.x;
    const int f4 = tid & 31;
    const int ts = tid >> 5;          // 0..7

    __shared__ float sb[8][PTV];                    // 4 KB beta tile
    __shared__ __align__(16) char pool[32768];      // staging 2x8KB; combine 32KB

    const uint32_t sp = smem_u32(pool);

    // beta tile: 8 s x 128 t = 256 float4
    {
        const float4* src = reinterpret_cast<const float4*>(beta + ((size_t)(b * PTH + s0) << 7));
        reinterpret_cast<float4*>(&sb[0][0])[tid] = src[tid];
    }

    // chunk = 16 t-rows x 128 f = 512 float4. Thread loads idx tid, tid+256.
    const float* vbase = v + (size_t)b * PTV * PF + f0;
    {
        const int r0 = tid >> 5, r1 = (tid + 256) >> 5, c = tid & 31;
        cp_async16(sp + tid * 16,         vbase + (size_t)r0 * PF + c * 4);
        cp_async16(sp + (tid + 256) * 16, vbase + (size_t)r1 * PF + c * 4);
    }
    CP_COMMIT();

    float4 acc[8];
#pragma unroll
    for (int s = 0; s < 8; s++) acc[s] = make_float4(0.f, 0.f, 0.f, 0.f);

    for (int ch = 0; ch < 8; ch++) {
        const int p = ch & 1;
        CP_WAIT(0);
        __syncthreads();            // chunk ch resident (+ sb published at ch=0)
        if (ch + 1 < 8) {
            const float* src = vbase + (size_t)(ch + 1) * 16 * PF;
            uint32_t dst = sp + (p ^ 1) * 8192;
            const int r0 = tid >> 5, r1 = (tid + 256) >> 5, c = tid & 31;
            cp_async16(dst + tid * 16,         src + (size_t)r0 * PF + c * 4);
            cp_async16(dst + (tid + 256) * 16, src + (size_t)r1 * PF + c * 4);
        }
        CP_COMMIT();

        const float4* vs = reinterpret_cast<const float4*>(pool + p * 8192);  // [16][32]
#pragma unroll
        for (int rr = 0; rr < 2; rr++) {
            const int r  = (ts << 1) + rr;
            const int tt = (ch << 4) + r;
            float4 vr = vs[r * 32 + f4];
#pragma unroll
            for (int s = 0; s < 8; s++) {
                float bb = sb[s][tt];
                acc[s].x += bb * vr.x;
                acc[s].y += bb * vr.y;
                acc[s].z += bb * vr.z;
                acc[s].w += bb * vr.w;
            }
        }
    }
    __syncthreads();               // staging reads done

    // combine across ts: pool as float4[ts 8][s 8][f4 32]
    float4* cmb = reinterpret_cast<float4*>(pool);
#pragma unroll
    for (int s = 0; s < 8; s++)
        cmb[((ts << 3) + s) * 32 + f4] = acc[s];
    __syncthreads();

    const int s_out = tid >> 5;
    const int fo = tid & 31;
    float4 sum = cmb[(s_out * 32) + fo];           // ts = 0
#pragma unroll
    for (int t2 = 1; t2 < 8; t2++) {
        float4 p4 = cmb[((t2 << 3) + s_out) * 32 + fo];
        sum.x += p4.x; sum.y += p4.y; sum.z += p4.z; sum.w += p4.w;
    }
    *reinterpret_cast<float4*>(
        u + (size_t)(b * PTH + s0 + s_out) * PF + f0 + (fo << 2)) = sum;
}

// ---------------------------------------------------------------------------
// kernel_launch
// Inputs: v [16,128,512], h [16,64,512], W [512,256], U [512,256], b [256], w [256,1]
// Output: u [16,64,512] float32
// ---------------------------------------------------------------------------
extern "C" void kernel_launch(void* const* d_in, const int* in_sizes, int n_in,
                              void* d_out, int out_size)
{
    const float* v    = (const float*)d_in[0];
    const float* h    = (const float*)d_in[1];
    const float* W    = (const float*)d_in[2];
    const float* U    = (const float*)d_in[3];
    const float* bvec = (const float*)d_in[4];
    const float* wvec = (const float*)d_in[5];
    float* out = (float*)d_out;

    float* beta_ptr; cudaGetSymbolAddress((void**)&beta_ptr, g_beta);

    prep_kernel<<<1024, 256>>>(v, h, W, U);
    mma_gemm_kernel<<<192, 256>>>(bvec);
    scores_kernel<<<dim3(PTH / 4, PB), 256>>>(wvec, beta_ptr);
    context_kernel<<<dim3(PF / 128, PTH / 8, PB), 256>>>(v, beta_ptr, out);
}